// round 13
// baseline (speedup 1.0000x reference)
#include <cuda_runtime.h>

#define N     8192
#define D     256
#define NCLS  10
#define NCH   8             // dim chunks (32 floats each)
#define CHW   32            // chunk width (floats)
#define NRG   32            // row groups
#define RPG   256           // rows per group
#define NBK   (NCH * NRG)   // 256 blocks
#define RPW   32            // rows per warp
#define RECF  340           // record: 320 S + 10 Q + 10 counts

// Scratch: records fully overwritten every replay; counters reset by final
// block -> graph-replay safe, no allocation, no zeroing kernel.
__device__ float  g_rec[NBK][RECF];   // 348 KB
__device__ double g_contrib[NCH];
__device__ int    g_gctr[NCH];
__device__ int    g_fctr;

// ---------------------------------------------------------------------------
// Single kernel, dimension-partitioned.
// Phase A (256 blocks, 2/SM): block (g,c) accumulates per-class sums for its
//   32 dims over its 256 rows. Lane = dim -> labels warp-uniform; 16 loads
//   front-batched per thread for MLP.
// Phase B (8 chunk leaders): sum 32 row-group records -> complete per-class
//   sums for the chunk -> fold to ONE scalar (all terms dim-separable).
// Phase C (last leader): sum 8 doubles, scale, store. Reset counters.
// ---------------------------------------------------------------------------
__global__ void __launch_bounds__(256) k_all(const float* __restrict__ x,
                                             const int* __restrict__ lab,
                                             float* __restrict__ res) {
    __shared__ int    labs[RPG];           // 1 KB
    __shared__ float  shS[8][NCLS * CHW];  // 10 KB
    __shared__ float  shQ[8][NCLS];
    __shared__ int    shC[8][NCLS];
    __shared__ float  tot[RECF];
    __shared__ float  x0c[CHW], xNc[CHW];
    __shared__ int    l0N[2];
    __shared__ int    flag;

    const int tid  = threadIdx.x;
    const int w    = tid >> 5;
    const int lane = tid & 31;
    const int b    = blockIdx.x;
    const int c    = b & (NCH - 1);        // dim chunk 0..7
    const int g    = b >> 3;               // row group 0..31

    // ---------------- Phase A ---------------------------------------------
    if (tid < RPG) labs[tid] = lab[g * RPG + tid];
    __syncthreads();

    float S[NCLS], Q[NCLS];
    int   C[NCLS];
    #pragma unroll
    for (int k = 0; k < NCLS; k++) { S[k] = 0.f; Q[k] = 0.f; C[k] = 0; }

    // Warp w handles rows [g*256 + w*32, +32); lane owns dim c*32+lane.
    const float* __restrict__ base =
        x + (size_t)(g * RPG + w * RPW) * D + c * CHW + lane;

#define BODY(k) { S[k] += v[j]; Q[k] += q; C[k]++; }
    #pragma unroll
    for (int r0 = 0; r0 < RPW; r0 += 16) {
        float v[16];
        int   ll[16];
        #pragma unroll
        for (int j = 0; j < 16; j++) v[j] = base[(r0 + j) * D];
        #pragma unroll
        for (int j = 0; j < 16; j++) ll[j] = labs[w * RPW + r0 + j];
        #pragma unroll
        for (int j = 0; j < 16; j++) {
            const int l = ll[j];           // uniform across warp
            const float q = v[j] * v[j];
            if      (l == 0) BODY(0)
            else if (l == 1) BODY(1)
            else if (l == 2) BODY(2)
            else if (l == 3) BODY(3)
            else if (l == 4) BODY(4)
            else if (l == 5) BODY(5)
            else if (l == 6) BODY(6)
            else if (l == 7) BODY(7)
            else if (l == 8) BODY(8)
            else             BODY(9)
        }
    }
#undef BODY

    // Per-warp dump: S per (class, dim); Q lane-reduced; counts from lane 0.
    #pragma unroll
    for (int k = 0; k < NCLS; k++) shS[w][k * CHW + lane] = S[k];
    #pragma unroll
    for (int k = 0; k < NCLS; k++) {
        float qv = Q[k];
        #pragma unroll
        for (int off = 16; off; off >>= 1)
            qv += __shfl_down_sync(0xffffffffu, qv, off);
        if (lane == 0) shQ[w][k] = qv;
    }
    if (lane == 0) {
        #pragma unroll
        for (int k = 0; k < NCLS; k++) shC[w][k] = C[k];
    }
    __syncthreads();

    // 8-warp merge -> record (340 floats).
    float* rec = g_rec[b];
    for (int i = tid; i < NCLS * CHW; i += 256) {
        float s = 0.f;
        #pragma unroll
        for (int ww = 0; ww < 8; ww++) s += shS[ww][i];
        rec[i] = s;
    }
    if (tid < NCLS) {
        float q = 0.f; int cc = 0;
        #pragma unroll
        for (int ww = 0; ww < 8; ww++) { q += shQ[ww][tid]; cc += shC[ww][tid]; }
        rec[NCLS * CHW + tid] = q;
        rec[NCLS * CHW + NCLS + tid] = (float)cc;
    }

    // ---------------- Phase B election (last of 32 per chunk) -------------
    __threadfence();
    __syncthreads();
    if (tid == 0) flag = (atomicAdd(&g_gctr[c], 1) == NRG - 1) ? 1 : 0;
    __syncthreads();
    if (!flag) return;
    __threadfence();   // acquire peers' records

    // Sum 32 row-group records (2 front-batched 16-load rounds, overlapped).
    for (int i = tid; i < RECF; i += 256) {
        float v[16], u[16];
        #pragma unroll
        for (int j = 0; j < 16; j++) v[j] = g_rec[j * NCH + c][i];
        #pragma unroll
        for (int j = 0; j < 16; j++) u[j] = g_rec[(16 + j) * NCH + c][i];
        float s = ((v[0] + v[1]) + (v[2] + v[3])) +
                  ((v[4] + v[5]) + (v[6] + v[7])) +
                  ((v[8] + v[9]) + (v[10] + v[11])) +
                  ((v[12] + v[13]) + (v[14] + v[15]));
        float s2 = ((u[0] + u[1]) + (u[2] + u[3])) +
                   ((u[4] + u[5]) + (u[6] + u[7])) +
                   ((u[8] + u[9]) + (u[10] + u[11])) +
                   ((u[12] + u[13]) + (u[14] + u[15]));
        tot[i] = s + s2;
    }
    if (w == 1) {
        x0c[lane] = x[c * CHW + lane];
        xNc[lane] = x[(size_t)(N - 1) * D + c * CHW + lane];
    }
    if (tid == 64) l0N[0] = lab[0];
    if (tid == 65) l0N[1] = lab[N - 1];
    __syncthreads();

    if (w == 0) {
        const int lab0 = l0N[0], labN = l0N[1];
        const float x0v = x0c[lane], xNv = xNc[lane];

        double dsame = 0.0;
        float satot = 0.f, sbtot = 0.f;
        #pragma unroll
        for (int l = 0; l < NCLS; l++) {
            float s  = tot[l * CHW + lane];
            float sa = s - ((l == labN) ? xNv : 0.f);   // rows i in [0, N-1)
            float sb = s - ((l == lab0) ? x0v : 0.f);   // cols j in [1, N)
            dsame += (double)sa * (double)sb;
            satot += sa; sbtot += sb;
        }
        double dall = (double)satot * (double)sbtot;
        double sq0  = (double)x0v * (double)x0v;
        double sqN  = (double)xNv * (double)xNv;

        #pragma unroll
        for (int off = 16; off; off >>= 1) {
            dsame += __shfl_down_sync(0xffffffffu, dsame, off);
            dall  += __shfl_down_sync(0xffffffffu, dall,  off);
            sq0   += __shfl_down_sync(0xffffffffu, sq0,   off);
            sqN   += __shfl_down_sync(0xffffffffu, sqN,   off);
        }

        if (lane == 0) {
            double term12 = 0.0;
            #pragma unroll
            for (int l = 0; l < NCLS; l++) {
                double Qc  = (double)tot[NCLS * CHW + l];          // chunk Q
                double cnt = (double)tot[NCLS * CHW + NCLS + l];   // global count
                double qA  = Qc - ((l == labN) ? sqN : 0.0);
                double qB  = Qc - ((l == lab0) ? sq0 : 0.0);
                double cA  = cnt - ((l == labN) ? 1.0 : 0.0);
                double cB  = cnt - ((l == lab0) ? 1.0 : 0.0);
                term12 += qA * (2.0 * cB - (double)(N - 1))
                        + qB * (2.0 * cA - (double)(N - 1));
            }
            g_contrib[c] = term12 - 2.0 * (2.0 * dsame - dall);
        }
    }

    // ---------------- Phase C election (last of 8 leaders) ----------------
    __threadfence();
    __syncthreads();
    if (tid == 0) flag = (atomicAdd(&g_fctr, 1) == NCH - 1) ? 1 : 0;
    __syncthreads();
    if (!flag) return;
    __threadfence();   // acquire contribs

    if (tid == 0) {
        double r = 0.0;
        #pragma unroll
        for (int c2 = 0; c2 < NCH; c2++) r += g_contrib[c2];  // fixed order
        res[0] = (float)(r * (0.5 / (double)N));              // COV*0.5/BATCH
    }
    // Reset counters for the next graph replay.
    if (tid < NCH) g_gctr[tid] = 0;
    if (tid == 0)  g_fctr = 0;
}

extern "C" void kernel_launch(void* const* d_in, const int* in_sizes, int n_in,
                              void* d_out, int out_size) {
    const float* x   = (const float*)d_in[0];
    const int*   lab = (const int*)d_in[1];
    float*       res = (float*)d_out;
    (void)in_sizes; (void)n_in; (void)out_size;

    k_all<<<NBK, 256>>>(x, lab, res);
}

// round 14
// speedup vs baseline: 1.3887x; 1.3887x over previous
#include <cuda_runtime.h>

#define N     8192
#define D     256
#define D4    64            // D/4 (float4 per row)
#define NCLS  10
#define NCH   2             // dim chunks of 128 dims
#define CH4   32            // float4 per row per chunk
#define NRG   64            // row groups per chunk
#define RPG   128           // rows per block
#define NBK   128           // blocks = NCH * NRG
#define RPW   16            // rows per warp
#define RECF  1300          // 1280 S + 10 Q + 10 counts (as float)
#define REC4  325           // RECF / 4
#define NMID  16            // mid reducers (8 per chunk)
#define MGS   8             // blocks per mid group

// Scratch: fully overwritten every replay; counters reset by final block.
__device__ float  g_rec[NBK][RECF];    // 666 KB
__device__ float  g_mid[NMID][RECF];
__device__ double g_contrib[NCH];
__device__ int    g_mctr[NMID];
__device__ int    g_cctr[NCH];
__device__ int    g_fctr;

// ---------------------------------------------------------------------------
// One kernel, 128 blocks (1 wave). Every stage's global reads are LDG.128
// with <=8 in flight and <=2 iterations -> <=2 round trips per stage.
//   A: block (g,c) streams 128 rows x 128 dims (float4, branch tree).
//   B: last of each 8-block mid-group sums 8 records (2x8 float4 RT).
//   C: last of each chunk's 8 mids sums 8 mid-records, runs dim-separable
//      epilogue for its 128 dims -> one double.
//   D: last of 2 combines, stores, resets counters.
// ---------------------------------------------------------------------------
__global__ void __launch_bounds__(256) k_all(const float* __restrict__ x,
                                             const int* __restrict__ lab,
                                             float* __restrict__ res) {
    __shared__ float4 shS[8][NCLS * 32];   // 40 KB
    __shared__ float  shQ[8][NCLS];
    __shared__ int    labs[RPG];
    __shared__ float  tot[RECF];           // 5.2 KB
    __shared__ double dred[4][4];
    __shared__ int    flag;

    const int tid  = threadIdx.x;
    const int w    = tid >> 5;
    const int lane = tid & 31;
    const int b    = blockIdx.x;
    const int c    = b & 1;                // chunk 0/1
    const int g    = b >> 1;               // row group 0..63
    const int m    = c * 8 + (g >> 3);     // mid group 0..15

    // ---------------- Phase A: stream 128 rows (float4) --------------------
    if (tid < RPG) labs[tid] = lab[g * RPG + tid];
    __syncthreads();

    float4 S[NCLS];
    float  Q[NCLS];
    #pragma unroll
    for (int k = 0; k < NCLS; k++) {
        S[k] = make_float4(0.f, 0.f, 0.f, 0.f);
        Q[k] = 0.f;
    }

    // Warp w: rows [g*128 + w*16, +16); lane owns dims c*128 + lane*4 .. +4.
    const float4* __restrict__ p =
        reinterpret_cast<const float4*>(x) +
        (size_t)(g * RPG + w * RPW) * D4 + c * CH4 + lane;

#define BODY(k) { S[k].x += v[r].x; S[k].y += v[r].y;                          \
                  S[k].z += v[r].z; S[k].w += v[r].w; Q[k] += q; }
    #pragma unroll
    for (int tile = 0; tile < 2; tile++) {
        float4 v[8];
        int    ll[8];
        #pragma unroll
        for (int r = 0; r < 8; r++) v[r] = p[(tile * 8 + r) * D4];
        #pragma unroll
        for (int r = 0; r < 8; r++) ll[r] = labs[w * RPW + tile * 8 + r];
        #pragma unroll
        for (int r = 0; r < 8; r++) {
            const int l = ll[r];           // uniform across warp
            float q = v[r].x * v[r].x;
            q = fmaf(v[r].y, v[r].y, q);
            q = fmaf(v[r].z, v[r].z, q);
            q = fmaf(v[r].w, v[r].w, q);
            if      (l == 0) BODY(0)
            else if (l == 1) BODY(1)
            else if (l == 2) BODY(2)
            else if (l == 3) BODY(3)
            else if (l == 4) BODY(4)
            else if (l == 5) BODY(5)
            else if (l == 6) BODY(6)
            else if (l == 7) BODY(7)
            else if (l == 8) BODY(8)
            else             BODY(9)
        }
    }
#undef BODY

    #pragma unroll
    for (int k = 0; k < NCLS; k++) shS[w][k * 32 + lane] = S[k];
    const int lane2 = lane;
    #pragma unroll
    for (int k = 0; k < NCLS; k++) {
        float qv = Q[k];
        #pragma unroll
        for (int off = 16; off; off >>= 1)
            qv += __shfl_down_sync(0xffffffffu, qv, off);
        if (lane2 == 0) shQ[w][k] = qv;
    }
    __syncthreads();

    // Merge 8 warps -> record (S as float4, Q and counts as scalars).
    float4* rec4 = reinterpret_cast<float4*>(g_rec[b]);
    for (int i = tid; i < NCLS * 32; i += 256) {
        float4 a = shS[0][i];
        #pragma unroll
        for (int ww = 1; ww < 8; ww++) {
            float4 u = shS[ww][i];
            a.x += u.x; a.y += u.y; a.z += u.z; a.w += u.w;
        }
        rec4[i] = a;
    }
    if (tid < NCLS) {
        float qs = 0.f;
        #pragma unroll
        for (int ww = 0; ww < 8; ww++) qs += shQ[ww][tid];
        g_rec[b][1280 + tid] = qs;
    }
    // Counts via ballots over the 128 cached labels (warp 0).
    if (w == 0) {
        #pragma unroll
        for (int k = 0; k < NCLS; k++) {
            int cc = 0;
            #pragma unroll
            for (int grp = 0; grp < 4; grp++) {
                unsigned bal = __ballot_sync(0xffffffffu,
                                             labs[grp * 32 + lane] == k);
                cc += __popc(bal);
            }
            if (lane == 0) g_rec[b][1290 + k] = (float)cc;
        }
    }

    // ---------------- Phase B election (last of 8 per mid group) ----------
    __threadfence();
    __syncthreads();
    if (tid == 0) flag = (atomicAdd(&g_mctr[m], 1) == MGS - 1) ? 1 : 0;
    __syncthreads();
    if (!flag) return;
    __threadfence();   // acquire peers' records

    {
        const int gk = (g >> 3) << 3;      // first row group of this mid
        float4* mid4 = reinterpret_cast<float4*>(g_mid[m]);
        for (int i = tid; i < REC4; i += 256) {
            float4 vv[MGS];
            #pragma unroll
            for (int j = 0; j < MGS; j++)
                vv[j] = reinterpret_cast<const float4*>(
                            g_rec[(gk + j) * 2 + c])[i];
            float4 a = vv[0];
            #pragma unroll
            for (int j = 1; j < MGS; j++) {
                a.x += vv[j].x; a.y += vv[j].y;
                a.z += vv[j].z; a.w += vv[j].w;
            }
            mid4[i] = a;
        }
    }

    // ---------------- Phase C election (last of 8 mids per chunk) ---------
    __threadfence();
    __syncthreads();
    if (tid == 0) flag = (atomicAdd(&g_cctr[c], 1) == 8 - 1) ? 1 : 0;
    __syncthreads();
    if (!flag) return;
    __threadfence();   // acquire mid records

    {
        float4* tot4 = reinterpret_cast<float4*>(tot);
        for (int i = tid; i < REC4; i += 256) {
            float4 vv[8];
            #pragma unroll
            for (int j = 0; j < 8; j++)
                vv[j] = reinterpret_cast<const float4*>(g_mid[c * 8 + j])[i];
            float4 a = vv[0];
            #pragma unroll
            for (int j = 1; j < 8; j++) {
                a.x += vv[j].x; a.y += vv[j].y;
                a.z += vv[j].z; a.w += vv[j].w;
            }
            tot4[i] = a;
        }
    }
    __syncthreads();

    // Epilogue for this chunk's 128 dims (threads 0..127).
    if (tid < 128) {
        const int t    = tid;
        const int lab0 = lab[0];
        const int labN = lab[N - 1];
        const float x0v = x[c * 128 + t];
        const float xNv = x[(size_t)(N - 1) * D + c * 128 + t];

        double dsame = 0.0;
        float satot = 0.f, sbtot = 0.f;
        #pragma unroll
        for (int l = 0; l < NCLS; l++) {
            float s  = tot[l * 128 + t];
            float sa = s - ((l == labN) ? xNv : 0.f);   // rows i in [0, N-1)
            float sb = s - ((l == lab0) ? x0v : 0.f);   // cols j in [1, N)
            dsame += (double)sa * (double)sb;
            satot += sa; sbtot += sb;
        }
        double dall = (double)satot * (double)sbtot;
        double sq0  = (double)x0v * (double)x0v;
        double sqN  = (double)xNv * (double)xNv;

        #pragma unroll
        for (int off = 16; off; off >>= 1) {
            dsame += __shfl_down_sync(0xffffffffu, dsame, off);
            dall  += __shfl_down_sync(0xffffffffu, dall,  off);
            sq0   += __shfl_down_sync(0xffffffffu, sq0,   off);
            sqN   += __shfl_down_sync(0xffffffffu, sqN,   off);
        }
        if (lane == 0) {
            dred[w][0] = dsame; dred[w][1] = dall;
            dred[w][2] = sq0;   dred[w][3] = sqN;
        }
    }
    __syncthreads();

    if (tid == 0) {
        double dsame = 0.0, dall = 0.0, sq0 = 0.0, sqN = 0.0;
        #pragma unroll
        for (int ww = 0; ww < 4; ww++) {
            dsame += dred[ww][0]; dall += dred[ww][1];
            sq0   += dred[ww][2]; sqN  += dred[ww][3];
        }
        const int lab0 = lab[0];
        const int labN = lab[N - 1];
        double term12 = 0.0;
        #pragma unroll
        for (int l = 0; l < NCLS; l++) {
            double Qc  = (double)tot[1280 + l];   // chunk sum-of-squares
            double cnt = (double)tot[1290 + l];   // global class count
            double qA  = Qc - ((l == labN) ? sqN : 0.0);
            double qB  = Qc - ((l == lab0) ? sq0 : 0.0);
            double cA  = cnt - ((l == labN) ? 1.0 : 0.0);
            double cB  = cnt - ((l == lab0) ? 1.0 : 0.0);
            term12 += qA * (2.0 * cB - (double)(N - 1))
                    + qB * (2.0 * cA - (double)(N - 1));
        }
        g_contrib[c] = term12 - 2.0 * (2.0 * dsame - dall);
    }

    // ---------------- Phase D election (last of 2 chunks) -----------------
    __threadfence();
    __syncthreads();
    if (tid == 0) flag = (atomicAdd(&g_fctr, 1) == NCH - 1) ? 1 : 0;
    __syncthreads();
    if (!flag) return;
    __threadfence();   // acquire contribs

    if (tid == 0)
        res[0] = (float)((g_contrib[0] + g_contrib[1]) * (0.5 / (double)N));
    // Reset counters for the next graph replay.
    if (tid < NMID) g_mctr[tid] = 0;
    if (tid < NCH)  g_cctr[tid] = 0;
    if (tid == 0)   g_fctr = 0;
}

extern "C" void kernel_launch(void* const* d_in, const int* in_sizes, int n_in,
                              void* d_out, int out_size) {
    const float* x   = (const float*)d_in[0];
    const int*   lab = (const int*)d_in[1];
    float*       res = (float*)d_out;
    (void)in_sizes; (void)n_in; (void)out_size;

    k_all<<<NBK, 256>>>(x, lab, res);
}